// round 4
// baseline (speedup 1.0000x reference)
#include <cuda_runtime.h>
#include <math_constants.h>

#define NP 100000          // nodes per type (N_P == N_A)
#define EDGES 500000
#define HD 128             // H*D
#define NH 4               // heads
#define PAD 132            // smem row stride (floats) to kill bank conflicts

// ---------------- scratch (device globals; no allocation allowed) ------------
__device__ float g_Whp  [(size_t)NP*HD];
__device__ float g_Wha  [(size_t)NP*HD];
__device__ float g_Whp2p[(size_t)NP*HD];
__device__ float g_Whp2a[(size_t)NP*HD];
__device__ float g_Wha2p[(size_t)NP*HD];
__device__ float g_Wha2a[(size_t)NP*HD];
__device__ float g_es[4*(size_t)NP*NH];   // per-relation src-node attn dots
__device__ float g_ed[4*(size_t)NP*NH];   // per-relation dst-node attn dots
__device__ float g_s [4*(size_t)NP*NH];   // segment sum of exp(e) -> 1/s
__device__ float g_e [4*(size_t)EDGES*NH];// per-edge exp(e)

// ---------------- helpers ----------------------------------------------------
__device__ __forceinline__ float leaky(float x) {
    return x > 0.f ? x : 0.2f * x;
}

__device__ __forceinline__ unsigned f2tf32(float f) {
    unsigned u;
    asm("cvt.rna.tf32.f32 %0, %1;" : "=r"(u) : "f"(f));
    return u;
}

__device__ __forceinline__ void redAddV4(float* p, float a, float b, float c, float d) {
    asm volatile("red.global.add.v4.f32 [%0], {%1,%2,%3,%4};"
                 :: "l"(p), "f"(a), "f"(b), "f"(c), "f"(d) : "memory");
}

__device__ __forceinline__ void mma_tf32(float d[4], const unsigned a[4],
                                         unsigned b0, unsigned b1) {
    asm volatile(
        "mma.sync.aligned.m16n8k8.row.col.f32.tf32.tf32.f32 "
        "{%0,%1,%2,%3}, {%4,%5,%6,%7}, {%8,%9}, {%0,%1,%2,%3};"
        : "+f"(d[0]), "+f"(d[1]), "+f"(d[2]), "+f"(d[3])
        : "r"(a[0]), "r"(a[1]), "r"(a[2]), "r"(a[3]), "r"(b0), "r"(b1));
}

// ---------------- small utility kernels --------------------------------------
__global__ void init_s() {
    int i = blockIdx.x * blockDim.x + threadIdx.x;
    if (i < 4 * NP * NH) g_s[i] = 0.f;
}

__global__ void inv_s() {
    int i = blockIdx.x * blockDim.x + threadIdx.x;
    if (i < 4 * NP * NH) {
        float v = g_s[i];
        g_s[i] = (v != 0.f) ? __frcp_rn(v) : 0.f;
    }
}

__global__ void relu_k(float4* __restrict__ out, int n4) {
    int i = blockIdx.x * blockDim.x + threadIdx.x;
    if (i < n4) {
        float4 v = out[i];
        v.x = fmaxf(v.x, 0.f); v.y = fmaxf(v.y, 0.f);
        v.z = fmaxf(v.z, 0.f); v.w = fmaxf(v.w, 0.f);
        out[i] = v;
    }
}

// ---------------- 3-in-1 tensor-core GEMM ------------------------------------
// One X tile (128 rows, K=128) shared by 3 weight matrices. B fragments are
// streamed straight from gmem (W is a 64KB broadcast operand -> L1/L2 resident)
// and converted to tf32 in registers. Smem holds only the A tile (67.5KB) so
// 2 blocks/SM fit -> 2x warps for latency hiding vs round 3.
struct Job {
    const float *W, *Bv, *att1, *att2;
    float *Wh, *acc2, *o1, *o2;
};
struct Jobs3 { Job j[3]; };

__global__ void gemm3(const float* __restrict__ X, int M, Jobs3 jobs)
{
    extern __shared__ float As[];     // 128 x PAD (tf32 bit patterns)
    const int tid  = threadIdx.x;
    const int row0 = blockIdx.x * 128;

    // load X tile [128][128] -> tf32, zero-pad past M
    #pragma unroll
    for (int i = 0; i < 16; i++) {
        int idx = tid + i * 256;          // float4 index (4096 total)
        int r = idx >> 5, c4 = idx & 31;
        int gr = row0 + r;
        float4 v = (gr < M) ? ((const float4*)X)[(size_t)gr * 32 + c4]
                            : make_float4(0.f, 0.f, 0.f, 0.f);
        float* d = As + r * PAD + c4 * 4;
        ((unsigned*)d)[0] = f2tf32(v.x);
        ((unsigned*)d)[1] = f2tf32(v.y);
        ((unsigned*)d)[2] = f2tf32(v.z);
        ((unsigned*)d)[3] = f2tf32(v.w);
    }
    __syncthreads();

    const int wid   = tid >> 5;
    const int lane  = tid & 31;
    const int warpM = wid & 3;        // 4 warps in M
    const int warpN = wid >> 2;       // 2 warps in N
    const int wm    = warpM * 32;
    const int wn    = warpN * 64;
    const int g     = lane >> 2;      // group id 0..7
    const int tig   = lane & 3;       // thread-in-group

    const unsigned* Au = (const unsigned*)As;

    #pragma unroll
    for (int j = 0; j < 3; j++) {
        const float* __restrict__ W    = jobs.j[j].W;
        const float* __restrict__ Bv   = jobs.j[j].Bv;
        const float* __restrict__ att1 = jobs.j[j].att1;
        const float* __restrict__ att2 = jobs.j[j].att2;
        float* __restrict__ Wh   = jobs.j[j].Wh;
        float* __restrict__ acc2 = jobs.j[j].acc2;
        float* __restrict__ o1   = jobs.j[j].o1;
        float* __restrict__ o2   = jobs.j[j].o2;

        float acc[2][8][4];
        #pragma unroll
        for (int mi = 0; mi < 2; mi++)
            #pragma unroll
            for (int ni = 0; ni < 8; ni++)
                #pragma unroll
                for (int q = 0; q < 4; q++) acc[mi][ni][q] = 0.f;

        #pragma unroll
        for (int kk = 0; kk < 16; kk++) {
            const int k0 = kk * 8;
            unsigned a[2][4];
            #pragma unroll
            for (int mi = 0; mi < 2; mi++) {
                int rb = wm + mi * 16;
                a[mi][0] = Au[(rb + g    ) * PAD + k0 + tig];
                a[mi][1] = Au[(rb + g + 8) * PAD + k0 + tig];
                a[mi][2] = Au[(rb + g    ) * PAD + k0 + tig + 4];
                a[mi][3] = Au[(rb + g + 8) * PAD + k0 + tig + 4];
            }
            #pragma unroll
            for (int ni = 0; ni < 8; ni++) {
                const int c = wn + ni * 8 + g;
                unsigned b0 = f2tf32(__ldg(W + (size_t)(k0 + tig    ) * HD + c));
                unsigned b1 = f2tf32(__ldg(W + (size_t)(k0 + tig + 4) * HD + c));
                mma_tf32(acc[0][ni], a[0], b0, b1);
                mma_tf32(acc[1][ni], a[1], b0, b1);
            }
        }

        // epilogue: bias, store Wh (+acc2), fused attention dot products
        float pa[2][2][2][2]; // [vec][mi][half][head_local]
        #pragma unroll
        for (int v = 0; v < 2; v++)
            #pragma unroll
            for (int mi = 0; mi < 2; mi++)
                #pragma unroll
                for (int hf = 0; hf < 2; hf++)
                    #pragma unroll
                    for (int hl = 0; hl < 2; hl++) pa[v][mi][hf][hl] = 0.f;

        #pragma unroll
        for (int ni = 0; ni < 8; ni++) {
            const int c0 = wn + ni * 8 + 2 * tig;
            const int hl = ni >> 2;       // head-local within warp (0/1)
            const float b0 = __ldg(Bv + c0), b1 = __ldg(Bv + c0 + 1);
            float a10 = 0.f, a11 = 0.f, a20 = 0.f, a21 = 0.f;
            if (att1) { a10 = __ldg(att1 + c0); a11 = __ldg(att1 + c0 + 1); }
            if (att2) { a20 = __ldg(att2 + c0); a21 = __ldg(att2 + c0 + 1); }
            #pragma unroll
            for (int mi = 0; mi < 2; mi++) {
                int r0 = row0 + wm + mi * 16 + g;
                float y00 = acc[mi][ni][0] + b0, y01 = acc[mi][ni][1] + b1; // row r0
                float y10 = acc[mi][ni][2] + b0, y11 = acc[mi][ni][3] + b1; // row r0+8
                if (r0 < M) {
                    *(float2*)(Wh + (size_t)r0 * HD + c0) = make_float2(y00, y01);
                    if (acc2) *(float2*)(acc2 + (size_t)r0 * HD + c0) = make_float2(y00, y01);
                }
                if (r0 + 8 < M) {
                    *(float2*)(Wh + (size_t)(r0 + 8) * HD + c0) = make_float2(y10, y11);
                    if (acc2) *(float2*)(acc2 + (size_t)(r0 + 8) * HD + c0) = make_float2(y10, y11);
                }
                pa[0][mi][0][hl] += y00 * a10 + y01 * a11;
                pa[0][mi][1][hl] += y10 * a10 + y11 * a11;
                pa[1][mi][0][hl] += y00 * a20 + y01 * a21;
                pa[1][mi][1][hl] += y10 * a20 + y11 * a21;
            }
        }

        #pragma unroll
        for (int v = 0; v < 2; v++) {
            float* o = (v == 0) ? o1 : o2;
            if (!o) continue;
            #pragma unroll
            for (int mi = 0; mi < 2; mi++)
                #pragma unroll
                for (int hf = 0; hf < 2; hf++)
                    #pragma unroll
                    for (int hl = 0; hl < 2; hl++) {
                        float p = pa[v][mi][hf][hl];
                        p += __shfl_down_sync(0xffffffffu, p, 2, 4);
                        p += __shfl_down_sync(0xffffffffu, p, 1, 4);
                        if (tig == 0) {
                            int r = row0 + wm + mi * 16 + hf * 8 + g;
                            if (r < M) o[(size_t)r * NH + warpN * 2 + hl] = p;
                        }
                    }
        }
    }
}

// ---------------- merged edge pass AB (all 4 relations) ----------------------
// ee = exp(leaky(es[src]+ed[dst])); segment-sum via red.v4.
// Softmax shift skipped: logits are O(5) so exp can't overflow, and softmax is
// shift-invariant -> identical result to the reference.
struct RelPtrs {
    const int* src[4];
    const int* dst[4];
    const float* whs[4];
    float* acc[4];
};

__global__ void edge_ab_all(RelPtrs rp, const float* __restrict__ esb,
                            const float* __restrict__ edb,
                            float* __restrict__ eb, float* __restrict__ sb)
{
    int i = blockIdx.x * blockDim.x + threadIdx.x;
    if (i >= 4 * EDGES) return;
    int r = i / EDGES;
    int e = i - r * EDGES;
    const size_t T = (size_t)NP * NH;
    int s = rp.src[r][e], d = rp.dst[r][e];
    float4 a = *(const float4*)(esb + r * T + (size_t)s * 4);
    float4 b = *(const float4*)(edb + r * T + (size_t)d * 4);
    float e0 = __expf(leaky(a.x + b.x));
    float e1 = __expf(leaky(a.y + b.y));
    float e2 = __expf(leaky(a.z + b.z));
    float e3 = __expf(leaky(a.w + b.w));
    *(float4*)(eb + (size_t)i * 4) = make_float4(e0, e1, e2, e3);
    redAddV4(sb + r * T + (size_t)d * 4, e0, e1, e2, e3);
}

// ---------------- merged edge pass C (all 4 relations) -----------------------
// One warp per edge; lane l owns 4 floats at col l*4 (head = l>>3).
__global__ void edge_c_all(RelPtrs rp, const float* __restrict__ eb,
                           const float* __restrict__ sb)
{
    long long gt = (long long)blockIdx.x * blockDim.x + threadIdx.x;
    long long w = gt >> 5;
    if (w >= 4LL * EDGES) return;
    int lane = (int)(gt & 31);
    int r = (int)(w / EDGES);
    int e = (int)(w - (long long)r * EDGES);
    const size_t T = (size_t)NP * NH;
    int s = rp.src[r][e], d = rp.dst[r][e];
    int h = lane >> 3;
    float a = eb[(size_t)w * 4 + h] * sb[r * T + (size_t)d * 4 + h];
    float4 v = *(const float4*)(rp.whs[r] + (size_t)s * HD + lane * 4);
    redAddV4(rp.acc[r] + (size_t)d * HD + lane * 4,
             v.x * a, v.y * a, v.z * a, v.w * a);
}

// -----------------------------------------------------------------------------
extern "C" void kernel_launch(void* const* d_in, const int* in_sizes, int n_in,
                              void* d_out, int out_size)
{
    const float* feat_P = (const float*)d_in[0];
    const float* feat_A = (const float*)d_in[1];
    const int* src[4] = { (const int*)d_in[2], (const int*)d_in[4],
                          (const int*)d_in[6], (const int*)d_in[8] };
    const int* dst[4] = { (const int*)d_in[3], (const int*)d_in[5],
                          (const int*)d_in[7], (const int*)d_in[9] };
    const float* W_P   = (const float*)d_in[10]; const float* b_P   = (const float*)d_in[11];
    const float* W_A   = (const float*)d_in[12]; const float* b_A   = (const float*)d_in[13];
    const float* W_p2p = (const float*)d_in[14]; const float* b_p2p = (const float*)d_in[15];
    const float* W_p2a = (const float*)d_in[16]; const float* b_p2a = (const float*)d_in[17];
    const float* W_a2p = (const float*)d_in[18]; const float* b_a2p = (const float*)d_in[19];
    const float* W_a2a = (const float*)d_in[20]; const float* b_a2a = (const float*)d_in[21];
    const float* att_src[4] = { (const float*)d_in[22], (const float*)d_in[24],
                                (const float*)d_in[26], (const float*)d_in[28] };
    const float* att_dst[4] = { (const float*)d_in[23], (const float*)d_in[25],
                                (const float*)d_in[27], (const float*)d_in[29] };

    float* out  = (float*)d_out;
    float* outP = out;
    float* outA = out + (size_t)NP * HD;

    float *whp, *wha, *whp2p, *whp2a, *wha2p, *wha2a, *esb, *edb, *sb, *eb;
    cudaGetSymbolAddress((void**)&whp,   g_Whp);
    cudaGetSymbolAddress((void**)&wha,   g_Wha);
    cudaGetSymbolAddress((void**)&whp2p, g_Whp2p);
    cudaGetSymbolAddress((void**)&whp2a, g_Whp2a);
    cudaGetSymbolAddress((void**)&wha2p, g_Wha2p);
    cudaGetSymbolAddress((void**)&wha2a, g_Wha2a);
    cudaGetSymbolAddress((void**)&esb,   g_es);
    cudaGetSymbolAddress((void**)&edb,   g_ed);
    cudaGetSymbolAddress((void**)&sb,    g_s);
    cudaGetSymbolAddress((void**)&eb,    g_e);

    const size_t SMEM = 128 * PAD * sizeof(float);   // 67584
    cudaFuncSetAttribute(gemm3, cudaFuncAttributeMaxDynamicSharedMemorySize, (int)SMEM);

    init_s<<<(4 * NP * NH + 255) / 256, 256>>>();

    const int GB = (NP + 127) / 128;
    const size_t T = (size_t)NP * NH;

    // P features: self transform (seeds outP, ed for relations 0/2) + p2p + p2a
    Jobs3 jp;
    jp.j[0] = { W_P,   b_P,   att_dst[0], att_dst[2], whp,   outP,    edb + 0 * T, edb + 2 * T };
    jp.j[1] = { W_p2p, b_p2p, att_src[0], nullptr,    whp2p, nullptr, esb + 0 * T, nullptr     };
    jp.j[2] = { W_p2a, b_p2a, att_src[1], nullptr,    whp2a, nullptr, esb + 1 * T, nullptr     };
    gemm3<<<GB, 256, SMEM>>>(feat_P, NP, jp);

    // A features: self transform (seeds outA, ed for relations 1/3) + a2p + a2a
    Jobs3 ja;
    ja.j[0] = { W_A,   b_A,   att_dst[1], att_dst[3], wha,   outA,    edb + 1 * T, edb + 3 * T };
    ja.j[1] = { W_a2p, b_a2p, att_src[2], nullptr,    wha2p, nullptr, esb + 2 * T, nullptr     };
    ja.j[2] = { W_a2a, b_a2a, att_src[3], nullptr,    wha2a, nullptr, esb + 3 * T, nullptr     };
    gemm3<<<GB, 256, SMEM>>>(feat_A, NP, ja);

    RelPtrs rp;
    for (int r = 0; r < 4; r++) {
        rp.src[r] = src[r];
        rp.dst[r] = dst[r];
        rp.acc[r] = (r == 0 || r == 2) ? outP : outA;
    }
    rp.whs[0] = whp2p; rp.whs[1] = whp2a; rp.whs[2] = wha2p; rp.whs[3] = wha2a;

    const int AB_B = (4 * EDGES + 255) / 256;
    edge_ab_all<<<AB_B, 256>>>(rp, esb, edb, eb, sb);

    inv_s<<<(4 * NP * NH + 255) / 256, 256>>>();

    const long long cthreads = 4LL * EDGES * 32;
    const int C_B = (int)((cthreads + 255) / 256);
    edge_c_all<<<C_B, 256>>>(rp, eb, sb);

    const int n4 = 2 * NP * HD / 4;
    relu_k<<<(n4 + 255) / 256, 256>>>((float4*)out, n4);
}

// round 7
// speedup vs baseline: 1.0635x; 1.0635x over previous
#include <cuda_runtime.h>
#include <math_constants.h>

#define NP 100000          // nodes per type (N_P == N_A)
#define EDGES 500000
#define HD 128             // H*D
#define NH 4               // heads
#define PAD 132            // smem row stride (floats) to kill bank conflicts

// ---------------- scratch (device globals; no allocation allowed) ------------
__device__ float g_Whp  [(size_t)NP*HD];
__device__ float g_Wha  [(size_t)NP*HD];
__device__ float g_Whp2p[(size_t)NP*HD];
__device__ float g_Whp2a[(size_t)NP*HD];
__device__ float g_Wha2p[(size_t)NP*HD];
__device__ float g_Wha2a[(size_t)NP*HD];
__device__ float g_es[4*(size_t)NP*NH];   // per-relation src-node attn dots
__device__ float g_ed[4*(size_t)NP*NH];   // per-relation dst-node attn dots
__device__ float g_s [4*(size_t)NP*NH];   // segment sum of exp(e) -> 1/s
__device__ float g_e [4*(size_t)EDGES*NH];// per-edge exp(e)

// ---------------- helpers ----------------------------------------------------
__device__ __forceinline__ float leaky(float x) {
    return x > 0.f ? x : 0.2f * x;
}

__device__ __forceinline__ unsigned f2tf32(float f) {
    unsigned u;
    asm("cvt.rna.tf32.f32 %0, %1;" : "=r"(u) : "f"(f));
    return u;
}

__device__ __forceinline__ void redAddV4(float* p, float a, float b, float c, float d) {
    asm volatile("red.global.add.v4.f32 [%0], {%1,%2,%3,%4};"
                 :: "l"(p), "f"(a), "f"(b), "f"(c), "f"(d) : "memory");
}

__device__ __forceinline__ void mma_tf32(float d[4], const unsigned a[4],
                                         unsigned b0, unsigned b1) {
    asm volatile(
        "mma.sync.aligned.m16n8k8.row.col.f32.tf32.tf32.f32 "
        "{%0,%1,%2,%3}, {%4,%5,%6,%7}, {%8,%9}, {%0,%1,%2,%3};"
        : "+f"(d[0]), "+f"(d[1]), "+f"(d[2]), "+f"(d[3])
        : "r"(a[0]), "r"(a[1]), "r"(a[2]), "r"(a[3]), "r"(b0), "r"(b1));
}

// ---------------- small utility kernels --------------------------------------
__global__ void init_s() {
    int i = blockIdx.x * blockDim.x + threadIdx.x;
    if (i < 4 * NP * NH) g_s[i] = 0.f;
}

__global__ void inv_s() {
    int i = blockIdx.x * blockDim.x + threadIdx.x;
    if (i < 4 * NP * NH) {
        float v = g_s[i];
        g_s[i] = (v != 0.f) ? __frcp_rn(v) : 0.f;
    }
}

__global__ void relu_k(float4* __restrict__ out, int n4) {
    int i = blockIdx.x * blockDim.x + threadIdx.x;
    if (i < n4) {
        float4 v = out[i];
        v.x = fmaxf(v.x, 0.f); v.y = fmaxf(v.y, 0.f);
        v.z = fmaxf(v.z, 0.f); v.w = fmaxf(v.w, 0.f);
        out[i] = v;
    }
}

// ---------------- 3-in-1 tensor-core GEMM, 128x128 tile, 256 threads ---------
// Round-3 proven geometry (8 warps: 4 in M x 2 in N, 102 regs) with two fixes:
//  (a) W loaded in two K=64 chunks -> smem = A(67.5KB)+W(33.8KB) = 101.4KB
//      -> 2 blocks/SM (round 3 had 135KB -> 1 block/SM, issue only 26%).
//  (b) 3 jobs share one A tile (X converted to tf32 once; 6 launches -> 2).
struct Job {
    const float *W, *Bv, *att1, *att2;
    float *Wh, *acc2, *o1, *o2;
};
struct Jobs3 { Job j[3]; };

__global__ void __launch_bounds__(256, 2)
gemm3(const float* __restrict__ X, int M, Jobs3 jobs)
{
    extern __shared__ float sm[];
    float* As = sm;               // 128 x PAD (tf32 bit patterns), full K=128
    float* Ws = sm + 128 * PAD;   // 64 x PAD, one K-chunk of W
    const int tid  = threadIdx.x;
    const int row0 = blockIdx.x * 128;

    // load X tile [128][128] -> tf32, zero-pad past M (4096 float4)
    #pragma unroll
    for (int i = 0; i < 16; i++) {
        int idx = tid + i * 256;
        int r = idx >> 5, c4 = idx & 31;
        int gr = row0 + r;
        float4 v = (gr < M) ? ((const float4*)X)[(size_t)gr * 32 + c4]
                            : make_float4(0.f, 0.f, 0.f, 0.f);
        float* d = As + r * PAD + c4 * 4;
        ((unsigned*)d)[0] = f2tf32(v.x);
        ((unsigned*)d)[1] = f2tf32(v.y);
        ((unsigned*)d)[2] = f2tf32(v.z);
        ((unsigned*)d)[3] = f2tf32(v.w);
    }

    const int wid   = tid >> 5;
    const int lane  = tid & 31;
    const int warpM = wid & 3;        // 4 warps in M (32 rows each)
    const int warpN = wid >> 2;       // 2 warps in N (64 cols each)
    const int wm    = warpM * 32;
    const int wn    = warpN * 64;
    const int g     = lane >> 2;      // group id 0..7
    const int tig   = lane & 3;       // thread-in-group

    const unsigned* Au = (const unsigned*)As;
    const unsigned* Wu = (const unsigned*)Ws;

    #pragma unroll
    for (int j = 0; j < 3; j++) {
        const float* __restrict__ W    = jobs.j[j].W;
        const float* __restrict__ Bv   = jobs.j[j].Bv;
        const float* __restrict__ att1 = jobs.j[j].att1;
        const float* __restrict__ att2 = jobs.j[j].att2;
        float* __restrict__ Wh   = jobs.j[j].Wh;
        float* __restrict__ acc2 = jobs.j[j].acc2;
        float* __restrict__ o1   = jobs.j[j].o1;
        float* __restrict__ o2   = jobs.j[j].o2;

        float acc[2][8][4];
        #pragma unroll
        for (int mi = 0; mi < 2; mi++)
            #pragma unroll
            for (int ni = 0; ni < 8; ni++)
                #pragma unroll
                for (int q = 0; q < 4; q++) acc[mi][ni][q] = 0.f;

        #pragma unroll
        for (int kh = 0; kh < 2; kh++) {
            // guard Ws against readers of the previous chunk/job; the first
            // pass also orders the A-tile stores above.
            __syncthreads();
            // load W rows [kh*64, kh*64+64) -> tf32 (2048 float4)
            #pragma unroll
            for (int i = 0; i < 8; i++) {
                int idx = tid + i * 256;
                int r = idx >> 5, c4 = idx & 31;
                float4 v = ((const float4*)W)[idx + kh * 2048];
                float* d = Ws + r * PAD + c4 * 4;
                ((unsigned*)d)[0] = f2tf32(v.x);
                ((unsigned*)d)[1] = f2tf32(v.y);
                ((unsigned*)d)[2] = f2tf32(v.z);
                ((unsigned*)d)[3] = f2tf32(v.w);
            }
            __syncthreads();

            #pragma unroll
            for (int kkk = 0; kkk < 8; kkk++) {
                const int k0  = kh * 64 + kkk * 8;   // global K for A
                const int k0l = kkk * 8;             // local K within W chunk
                unsigned a[2][4];
                #pragma unroll
                for (int mi = 0; mi < 2; mi++) {
                    int rb = wm + mi * 16;
                    a[mi][0] = Au[(rb + g    ) * PAD + k0 + tig];
                    a[mi][1] = Au[(rb + g + 8) * PAD + k0 + tig];
                    a[mi][2] = Au[(rb + g    ) * PAD + k0 + tig + 4];
                    a[mi][3] = Au[(rb + g + 8) * PAD + k0 + tig + 4];
                }
                #pragma unroll
                for (int ni = 0; ni < 8; ni++) {
                    unsigned b0 = Wu[(k0l + tig    ) * PAD + wn + ni * 8 + g];
                    unsigned b1 = Wu[(k0l + tig + 4) * PAD + wn + ni * 8 + g];
                    mma_tf32(acc[0][ni], a[0], b0, b1);
                    mma_tf32(acc[1][ni], a[1], b0, b1);
                }
            }
        }

        // epilogue: bias, store Wh (+acc2), fused attention dot products
        float pa[2][2][2][2]; // [vec][mi][half][head_local]
        #pragma unroll
        for (int v = 0; v < 2; v++)
            #pragma unroll
            for (int mi = 0; mi < 2; mi++)
                #pragma unroll
                for (int hf = 0; hf < 2; hf++)
                    #pragma unroll
                    for (int hl = 0; hl < 2; hl++) pa[v][mi][hf][hl] = 0.f;

        #pragma unroll
        for (int ni = 0; ni < 8; ni++) {
            const int c0 = wn + ni * 8 + 2 * tig;
            const int hl = ni >> 2;       // head-local within warp (0/1)
            const float b0 = __ldg(Bv + c0), b1 = __ldg(Bv + c0 + 1);
            float a10 = 0.f, a11 = 0.f, a20 = 0.f, a21 = 0.f;
            if (att1) { a10 = __ldg(att1 + c0); a11 = __ldg(att1 + c0 + 1); }
            if (att2) { a20 = __ldg(att2 + c0); a21 = __ldg(att2 + c0 + 1); }
            #pragma unroll
            for (int mi = 0; mi < 2; mi++) {
                int r0 = row0 + wm + mi * 16 + g;
                float y00 = acc[mi][ni][0] + b0, y01 = acc[mi][ni][1] + b1; // row r0
                float y10 = acc[mi][ni][2] + b0, y11 = acc[mi][ni][3] + b1; // row r0+8
                if (r0 < M) {
                    *(float2*)(Wh + (size_t)r0 * HD + c0) = make_float2(y00, y01);
                    if (acc2) *(float2*)(acc2 + (size_t)r0 * HD + c0) = make_float2(y00, y01);
                }
                if (r0 + 8 < M) {
                    *(float2*)(Wh + (size_t)(r0 + 8) * HD + c0) = make_float2(y10, y11);
                    if (acc2) *(float2*)(acc2 + (size_t)(r0 + 8) * HD + c0) = make_float2(y10, y11);
                }
                pa[0][mi][0][hl] += y00 * a10 + y01 * a11;
                pa[0][mi][1][hl] += y10 * a10 + y11 * a11;
                pa[1][mi][0][hl] += y00 * a20 + y01 * a21;
                pa[1][mi][1][hl] += y10 * a20 + y11 * a21;
            }
        }

        #pragma unroll
        for (int v = 0; v < 2; v++) {
            float* o = (v == 0) ? o1 : o2;
            if (!o) continue;
            #pragma unroll
            for (int mi = 0; mi < 2; mi++)
                #pragma unroll
                for (int hf = 0; hf < 2; hf++)
                    #pragma unroll
                    for (int hl = 0; hl < 2; hl++) {
                        float p = pa[v][mi][hf][hl];
                        p += __shfl_down_sync(0xffffffffu, p, 2, 4);
                        p += __shfl_down_sync(0xffffffffu, p, 1, 4);
                        if (tig == 0) {
                            int r = row0 + wm + mi * 16 + hf * 8 + g;
                            if (r < M) o[(size_t)r * NH + warpN * 2 + hl] = p;
                        }
                    }
        }
    }
}

// ---------------- merged edge pass AB (all 4 relations) ----------------------
// ee = exp(leaky(es[src]+ed[dst])); segment-sum via red.v4.
// Softmax shift skipped: logits are O(5) so exp can't overflow, and softmax is
// shift-invariant -> identical result to the reference.
struct RelPtrs {
    const int* src[4];
    const int* dst[4];
    const float* whs[4];
    float* acc[4];
};

__global__ void edge_ab_all(RelPtrs rp, const float* __restrict__ esb,
                            const float* __restrict__ edb,
                            float* __restrict__ eb, float* __restrict__ sb)
{
    int i = blockIdx.x * blockDim.x + threadIdx.x;
    if (i >= 4 * EDGES) return;
    int r = i / EDGES;
    int e = i - r * EDGES;
    const size_t T = (size_t)NP * NH;
    int s = rp.src[r][e], d = rp.dst[r][e];
    float4 a = *(const float4*)(esb + r * T + (size_t)s * 4);
    float4 b = *(const float4*)(edb + r * T + (size_t)d * 4);
    float e0 = __expf(leaky(a.x + b.x));
    float e1 = __expf(leaky(a.y + b.y));
    float e2 = __expf(leaky(a.z + b.z));
    float e3 = __expf(leaky(a.w + b.w));
    *(float4*)(eb + (size_t)i * 4) = make_float4(e0, e1, e2, e3);
    redAddV4(sb + r * T + (size_t)d * 4, e0, e1, e2, e3);
}

// ---------------- merged edge pass C (all 4 relations) -----------------------
// One warp per edge; lane l owns 4 floats at col l*4 (head = l>>3).
__global__ void edge_c_all(RelPtrs rp, const float* __restrict__ eb,
                           const float* __restrict__ sb)
{
    long long gt = (long long)blockIdx.x * blockDim.x + threadIdx.x;
    long long w = gt >> 5;
    if (w >= 4LL * EDGES) return;
    int lane = (int)(gt & 31);
    int r = (int)(w / EDGES);
    int e = (int)(w - (long long)r * EDGES);
    const size_t T = (size_t)NP * NH;
    int s = rp.src[r][e], d = rp.dst[r][e];
    int h = lane >> 3;
    float a = eb[(size_t)w * 4 + h] * sb[r * T + (size_t)d * 4 + h];
    float4 v = *(const float4*)(rp.whs[r] + (size_t)s * HD + lane * 4);
    redAddV4(rp.acc[r] + (size_t)d * HD + lane * 4,
             v.x * a, v.y * a, v.z * a, v.w * a);
}

// -----------------------------------------------------------------------------
extern "C" void kernel_launch(void* const* d_in, const int* in_sizes, int n_in,
                              void* d_out, int out_size)
{
    const float* feat_P = (const float*)d_in[0];
    const float* feat_A = (const float*)d_in[1];
    const int* src[4] = { (const int*)d_in[2], (const int*)d_in[4],
                          (const int*)d_in[6], (const int*)d_in[8] };
    const int* dst[4] = { (const int*)d_in[3], (const int*)d_in[5],
                          (const int*)d_in[7], (const int*)d_in[9] };
    const float* W_P   = (const float*)d_in[10]; const float* b_P   = (const float*)d_in[11];
    const float* W_A   = (const float*)d_in[12]; const float* b_A   = (const float*)d_in[13];
    const float* W_p2p = (const float*)d_in[14]; const float* b_p2p = (const float*)d_in[15];
    const float* W_p2a = (const float*)d_in[16]; const float* b_p2a = (const float*)d_in[17];
    const float* W_a2p = (const float*)d_in[18]; const float* b_a2p = (const float*)d_in[19];
    const float* W_a2a = (const float*)d_in[20]; const float* b_a2a = (const float*)d_in[21];
    const float* att_src[4] = { (const float*)d_in[22], (const float*)d_in[24],
                                (const float*)d_in[26], (const float*)d_in[28] };
    const float* att_dst[4] = { (const float*)d_in[23], (const float*)d_in[25],
                                (const float*)d_in[27], (const float*)d_in[29] };

    float* out  = (float*)d_out;
    float* outP = out;
    float* outA = out + (size_t)NP * HD;

    float *whp, *wha, *whp2p, *whp2a, *wha2p, *wha2a, *esb, *edb, *sb, *eb;
    cudaGetSymbolAddress((void**)&whp,   g_Whp);
    cudaGetSymbolAddress((void**)&wha,   g_Wha);
    cudaGetSymbolAddress((void**)&whp2p, g_Whp2p);
    cudaGetSymbolAddress((void**)&whp2a, g_Whp2a);
    cudaGetSymbolAddress((void**)&wha2p, g_Wha2p);
    cudaGetSymbolAddress((void**)&wha2a, g_Wha2a);
    cudaGetSymbolAddress((void**)&esb,   g_es);
    cudaGetSymbolAddress((void**)&edb,   g_ed);
    cudaGetSymbolAddress((void**)&sb,    g_s);
    cudaGetSymbolAddress((void**)&eb,    g_e);

    const size_t SMEM = (128 + 64) * PAD * sizeof(float);   // 101376
    cudaFuncSetAttribute(gemm3, cudaFuncAttributeMaxDynamicSharedMemorySize, (int)SMEM);

    init_s<<<(4 * NP * NH + 255) / 256, 256>>>();

    const int GB = (NP + 127) / 128;
    const size_t T = (size_t)NP * NH;

    // P features: self transform (seeds outP, ed for relations 0/2) + p2p + p2a
    Jobs3 jp;
    jp.j[0] = { W_P,   b_P,   att_dst[0], att_dst[2], whp,   outP,    edb + 0 * T, edb + 2 * T };
    jp.j[1] = { W_p2p, b_p2p, att_src[0], nullptr,    whp2p, nullptr, esb + 0 * T, nullptr     };
    jp.j[2] = { W_p2a, b_p2a, att_src[1], nullptr,    whp2a, nullptr, esb + 1 * T, nullptr     };
    gemm3<<<GB, 256, SMEM>>>(feat_P, NP, jp);

    // A features: self transform (seeds outA, ed for relations 1/3) + a2p + a2a
    Jobs3 ja;
    ja.j[0] = { W_A,   b_A,   att_dst[1], att_dst[3], wha,   outA,    edb + 1 * T, edb + 3 * T };
    ja.j[1] = { W_a2p, b_a2p, att_src[2], nullptr,    wha2p, nullptr, esb + 2 * T, nullptr     };
    ja.j[2] = { W_a2a, b_a2a, att_src[3], nullptr,    wha2a, nullptr, esb + 3 * T, nullptr     };
    gemm3<<<GB, 256, SMEM>>>(feat_A, NP, ja);

    RelPtrs rp;
    for (int r = 0; r < 4; r++) {
        rp.src[r] = src[r];
        rp.dst[r] = dst[r];
        rp.acc[r] = (r == 0 || r == 2) ? outP : outA;
    }
    rp.whs[0] = whp2p; rp.whs[1] = whp2a; rp.whs[2] = wha2p; rp.whs[3] = wha2a;

    const int AB_B = (4 * EDGES + 255) / 256;
    edge_ab_all<<<AB_B, 256>>>(rp, esb, edb, eb, sb);

    inv_s<<<(4 * NP * NH + 255) / 256, 256>>>();

    const long long cthreads = 4LL * EDGES * 32;
    const int C_B = (int)((cthreads + 255) / 256);
    edge_c_all<<<C_B, 256>>>(rp, eb, sb);

    const int n4 = 2 * NP * HD / 4;
    relu_k<<<(n4 + 255) / 256, 256>>>((float4*)out, n4);
}